// round 8
// baseline (speedup 1.0000x reference)
#include <cuda_runtime.h>
#include <cuda_bf16.h>

// Segment-sum scatter at the LTS/atomic structural floor (~50us kernel).
//
// Confirmed model (R1/R3/R6 invariance at 50.0-50.9us vs R2/R4/R5 regressions):
// the kernel saturates the L2 subsystem — 218MB read-fill + 205MB RED payload
// through the crossbar (~8.5TB/s) plus slice-internal RMW (read+write 205MB
// each) lands on the ~6300 B/cyc LTS cap + atomic-ALU slots. All bytes are
// irreducible: edge_w read once (no reuse), 16B max RED width, bf16 payload
// fails the 1e-3 budget, dedup has ~0 expected hits on uniform-random indices,
// per-replay zeroing is mandatory.
//
// Proven-optimal shape: TPB=256, 4 quads/thread grid-strided by total thread
// count. Warp loads 32 consecutive float4s = 4 x 128B lines per LDG.128;
// 4 lanes share one broadcast src int; 8 loads front-batched (MLP_p1=8) ahead
// of 4 fire-and-forget RED.E.ADD.F32.V4 (each edge's 4 lanes cover one 64B
// output line -> one coalesced atomic wavefront). edge_w streams evict-first
// (__ldcs) so the 6.4MB destination region stays L2-resident for the RMWs.
//
// Fixed sizes: E = 3,200,000, F = 16 -> 12.8M quads = 3.2M threads x 4.

#define E_TOTAL   3200000
#define NUM_QUADS (E_TOTAL * 4)
#define TPB       256
#define QPT       4
#define TOTAL_THREADS (NUM_QUADS / QPT)        // 3,200,000
#define NBLK          (TOTAL_THREADS / TPB)    // 12,500

__global__ void __launch_bounds__(TPB)
spmm_scatter_kernel(const int* __restrict__ src,
                    const float4* __restrict__ w4,   // [E*4] float4
                    float4* __restrict__ out4)       // [N*4] float4
{
    const int tid = blockIdx.x * TPB + threadIdx.x;
    const int S   = TOTAL_THREADS;

    const int i0 = tid;
    const int i1 = tid + S;
    const int i2 = tid + 2 * S;
    const int i3 = tid + 3 * S;

    // Front-batched independent loads (ptxas hoists these together, MLP ~8).
    int s0 = __ldg(&src[i0 >> 2]);
    int s1 = __ldg(&src[i1 >> 2]);
    int s2 = __ldg(&src[i2 >> 2]);
    int s3 = __ldg(&src[i3 >> 2]);

    float4 v0 = __ldcs(&w4[i0]);   // evict-first: edge_w streams once,
    float4 v1 = __ldcs(&w4[i1]);   // keep L2 for the atomic destinations
    float4 v2 = __ldcs(&w4[i2]);
    float4 v3 = __ldcs(&w4[i3]);

    atomicAdd(&out4[((size_t)s0 << 2) + (i0 & 3)], v0);
    atomicAdd(&out4[((size_t)s1 << 2) + (i1 & 3)], v1);
    atomicAdd(&out4[((size_t)s2 << 2) + (i2 & 3)], v2);
    atomicAdd(&out4[((size_t)s3 << 2) + (i3 & 3)], v3);
}

extern "C" void kernel_launch(void* const* d_in, const int* in_sizes, int n_in,
                              void* d_out, int out_size)
{
    const int*   edge   = (const int*)d_in[0];   // edge[0] = src, first E ints
    const float* edge_w = (const float*)d_in[1];

    // d_out poisoned to 0xAA -> zero it (memset node is graph-capturable);
    // also pre-warms the 6.4 MB destination region in L2. Mandatory every
    // replay: REDs accumulate otherwise.
    cudaMemsetAsync(d_out, 0, (size_t)out_size * sizeof(float), 0);

    spmm_scatter_kernel<<<NBLK, TPB>>>(
        edge,
        (const float4*)edge_w,
        (float4*)d_out);
}